// round 1
// baseline (speedup 1.0000x reference)
#include <cuda_runtime.h>
#include <cuda_bf16.h>
#include <math.h>

// Problem constants (fixed by reference: N=1024, L=30, G=10000, NB=64)
#define NCELLS 1024
#define LDIM   30
#define NBATCH 64
#define G_TILE 128
#define CHUNK  64

// Scratch (no cudaMalloc allowed): permutation of cells grouped by batch + batch offsets
__device__ int g_perm[NCELLS];
__device__ int g_start[NBATCH + 1];

// ---------------------------------------------------------------------------
// Kernel 1: counting sort of cell indices by batch id. One block, N threads.
// ---------------------------------------------------------------------------
__global__ void sort_by_batch_kernel(const int* __restrict__ batch, int N, int NB) {
    __shared__ int cnt[NBATCH];
    __shared__ int off[NBATCH + 1];
    int t = threadIdx.x;
    if (t < NB) cnt[t] = 0;
    __syncthreads();
    int b = -1;
    if (t < N) { b = batch[t]; atomicAdd(&cnt[b], 1); }
    __syncthreads();
    if (t == 0) {
        int s = 0;
        for (int i = 0; i < NB; i++) { off[i] = s; s += cnt[i]; }
        off[NB] = s;
    }
    __syncthreads();
    // publish starts BEFORE off[] gets mutated by the placement atomics
    if (t <= NB) g_start[t] = off[t];
    __syncthreads();
    if (t < N) {
        int pos = atomicAdd(&off[b], 1);
        g_perm[pos] = t;
    }
}

// ---------------------------------------------------------------------------
// Kernel 2: main decoder.
// grid = (ceil(G/G_TILE), NB), block = G_TILE threads (1 thread = 1 gene).
// Each thread keeps combined coefficients c[l] = W[l,g] + A[b,g,l] in regs,
// then streams the batch's cells (z rows staged in smem; reads are broadcast).
// ---------------------------------------------------------------------------
__global__ __launch_bounds__(G_TILE) void decoder_kernel(
    const float* __restrict__ z,      // [N, L]
    const float* __restrict__ sf,     // [N, 1]
    const float* __restrict__ W,      // [L, G]
    const float* __restrict__ A,      // [NB, G, L]
    const float* __restrict__ bemb,   // [NB, G]
    float* __restrict__ out,          // [N, G]
    int G)
{
    const int b = blockIdx.y;
    const int s = g_start[b];
    const int e = g_start[b + 1];
    if (s == e) return;                       // no cells in this batch (uniform per block)

    const int g = blockIdx.x * G_TILE + threadIdx.x;
    const bool active = (g < G);

    float c[LDIM];
    float bias = 0.0f;
    if (active) {
        const float* Ap = A + ((size_t)b * G + g) * LDIM;
        #pragma unroll
        for (int l = 0; l < LDIM; l++)
            c[l] = W[(size_t)l * G + g] + Ap[l];   // both coalesced/line-covered
        bias = bemb[(size_t)b * G + g];
    }

    __shared__ float zs[CHUNK][LDIM];
    __shared__ float sfs[CHUNK];
    __shared__ int   cells[CHUNK];

    for (int c0 = s; c0 < e; c0 += CHUNK) {
        const int nc = min(CHUNK, e - c0);
        __syncthreads();   // protect previous iteration's smem reads
        for (int i = threadIdx.x; i < nc; i += G_TILE) {
            int cell = g_perm[c0 + i];
            cells[i] = cell;
            sfs[i]   = sf[cell];
        }
        for (int i = threadIdx.x; i < nc * LDIM; i += G_TILE) {
            int ci = i / LDIM, l = i - ci * LDIM;
            zs[ci][l] = z[(size_t)g_perm[c0 + ci] * LDIM + l];
        }
        __syncthreads();
        if (active) {
            for (int i = 0; i < nc; i++) {
                float acc = bias;
                #pragma unroll
                for (int l = 0; l < LDIM; l++)
                    acc = fmaf(c[l], zs[i][l], acc);     // zs: broadcast LDS
                // softplus(x) = max(x,0) + log1p(exp(-|x|))  (matches jax.nn.softplus)
                float sp = fmaxf(acc, 0.0f) + log1pf(expf(-fabsf(acc)));
                out[(size_t)cells[i] * G + g] = sp * sfs[i];   // coalesced 512B row
            }
        }
    }
}

// ---------------------------------------------------------------------------
// Kernel 3: inverse_dispersion = exp(px_r)  -> out[N*G : N*G+G]
// ---------------------------------------------------------------------------
__global__ void exp_kernel(const float* __restrict__ px_r, float* __restrict__ out, int G) {
    int g = blockIdx.x * blockDim.x + threadIdx.x;
    if (g < G) out[g] = expf(px_r[g]);
}

// ---------------------------------------------------------------------------
// Inputs (metadata order): z, batch_covariate, size_factor, W_amat, A_emb,
//                          b_emb, px_r.  Output: mean [N,G] ++ inv_disp [G].
// ---------------------------------------------------------------------------
extern "C" void kernel_launch(void* const* d_in, const int* in_sizes, int n_in,
                              void* d_out, int out_size) {
    const float* z    = (const float*)d_in[0];
    const int*   bc   = (const int*)  d_in[1];
    const float* sf   = (const float*)d_in[2];
    const float* W    = (const float*)d_in[3];
    const float* A    = (const float*)d_in[4];
    const float* bemb = (const float*)d_in[5];
    const float* px_r = (const float*)d_in[6];
    float* out = (float*)d_out;

    const int N  = in_sizes[1];        // batch_covariate count = N (1024)
    const int G  = in_sizes[6];        // px_r count = G (10000)
    const int NB = in_sizes[5] / G;    // b_emb = NB*G (64)

    sort_by_batch_kernel<<<1, NCELLS>>>(bc, N, NB);

    dim3 grid((G + G_TILE - 1) / G_TILE, NB);
    decoder_kernel<<<grid, G_TILE>>>(z, sf, W, A, bemb, out, G);

    exp_kernel<<<(G + 255) / 256, 256>>>(px_r, out + (size_t)N * G, G);
}

// round 3
// speedup vs baseline: 1.1228x; 1.1228x over previous
#include <cuda_runtime.h>
#include <cuda_bf16.h>
#include <math.h>

// Problem constants (fixed by reference: N=1024, L=30, G=10000, NB=64)
#define NMAX    1024
#define LDIM    30
#define GPB     256          // genes per block
#define THREADS 128          // 2 genes per thread
#define CHUNK   64           // cells staged per smem chunk
#define ZROW    32           // padded z row (floats) for alignment/banks

__device__ __forceinline__ float softplus_f(float x) {
    // matches jax.nn.softplus: max(x,0) + log1p(exp(-|x|))
    return fmaxf(x, 0.0f) + log1pf(expf(-fabsf(x)));
}

// ---------------------------------------------------------------------------
// Single fused kernel.
// grid = (ceil(G/GPB), NB+1), block = THREADS.
//  y < NB : decoder for batch y over a 256-gene tile
//  y == NB: inverse_dispersion = exp(px_r)
// ---------------------------------------------------------------------------
__global__ __launch_bounds__(THREADS) void fused_decoder_kernel(
    const float* __restrict__ z,      // [N, L]
    const int*   __restrict__ bc,     // [N]
    const float* __restrict__ sf,     // [N, 1]
    const float* __restrict__ W,      // [L, G]
    const float* __restrict__ A,      // [NB, G, L]
    const float* __restrict__ bemb,   // [NB, G]
    const float* __restrict__ px_r,   // [G]
    float* __restrict__ out,          // [N, G] ++ [G]
    int N, int G, int NB)
{
    const int b = blockIdx.y;

    // ---- exp(px_r) slice ----
    if (b == NB) {
        int g0 = blockIdx.x * GPB + threadIdx.x * 2;
        float* od = out + (size_t)N * G;
        if (g0 < G)     od[g0]     = expf(px_r[g0]);
        if (g0 + 1 < G) od[g0 + 1] = expf(px_r[g0 + 1]);
        return;
    }

    __shared__ float sbuf[GPB * LDIM];   // 7680 floats: A stage, then reused for z chunks
    __shared__ int   cells[NMAX];
    __shared__ float sfs[NMAX];
    __shared__ int   scount;

    // ---- self-compact this batch's cell list (bc is 4KB, L1-resident) ----
    if (threadIdx.x == 0) scount = 0;
    __syncthreads();
    for (int n = threadIdx.x; n < N; n += THREADS) {
        if (bc[n] == b) {
            int p = atomicAdd(&scount, 1);
            cells[p] = n;
        }
    }
    __syncthreads();
    const int ncell = scount;
    if (ncell == 0) return;
    for (int i = threadIdx.x; i < ncell; i += THREADS) sfs[i] = sf[cells[i]];

    // ---- stage A tile coalesced (float4), then extract per-thread coeffs ----
    const int gbase = blockIdx.x * GPB;
    const int nst   = min(GPB, G - gbase);            // genes in tile (even)
    {
        // word offset (b*G + gbase)*30: gbase multiple of 256 -> *30 mult of 7680;
        // b*G*30 = b*300000 (mult of 4) -> 16B-aligned. nst*30 mult of 4.
        const float4* Ap4 = (const float4*)(A + ((size_t)b * G + gbase) * LDIM);
        float4* sb4 = (float4*)sbuf;
        const int nw4 = (nst * LDIM) >> 2;
        for (int i = threadIdx.x; i < nw4; i += THREADS) sb4[i] = Ap4[i];
    }
    __syncthreads();

    const int t2 = threadIdx.x * 2;
    const int g0 = gbase + t2;
    const bool act = (t2 < nst);

    float c0[LDIM], c1[LDIM];
    float bias0 = 0.0f, bias1 = 0.0f;
    if (act) {
        #pragma unroll
        for (int l = 0; l < LDIM; l++) {
            // W row: g0 even, G even -> 8B-aligned float2, coalesced
            float2 w = *(const float2*)(W + (size_t)l * G + g0);
            c0[l] = w.x + sbuf[t2 * LDIM + l];
            c1[l] = w.y + sbuf[(t2 + 1) * LDIM + l];
        }
        float2 bb = *(const float2*)(bemb + (size_t)b * G + g0);
        bias0 = bb.x; bias1 = bb.y;
    }
    __syncthreads();   // done with A stage; reuse sbuf for z chunks

    float* zs = sbuf;  // [CHUNK][ZROW] = 2048 floats <= 7680

    for (int cc = 0; cc < ncell; cc += CHUNK) {
        const int nc = min(CHUNK, ncell - cc);
        __syncthreads();   // previous chunk's reads complete
        // stage z rows as float2 (z row word-offset cell*30 is even -> 8B aligned)
        for (int i = threadIdx.x; i < nc * (LDIM / 2); i += THREADS) {
            int ci = i / (LDIM / 2), j = i - ci * (LDIM / 2);
            float2 v = *(const float2*)(z + (size_t)cells[cc + ci] * LDIM + 2 * j);
            *(float2*)(zs + ci * ZROW + 2 * j) = v;
        }
        __syncthreads();

        if (act) {
            for (int i = 0; i < nc; i += 2) {
                const bool two = (i + 1 < nc);
                const float2* zr0 = (const float2*)(zs + i * ZROW);
                const float2* zr1 = (const float2*)(zs + (two ? i + 1 : i) * ZROW);
                float a00 = bias0, a01 = bias1, a10 = bias0, a11 = bias1;
                #pragma unroll
                for (int l = 0; l < LDIM / 2; l++) {
                    float2 zv0 = zr0[l];                 // broadcast LDS.64
                    float2 zv1 = zr1[l];
                    a00 = fmaf(c0[2*l],   zv0.x, a00);
                    a01 = fmaf(c1[2*l],   zv0.x, a01);
                    a10 = fmaf(c0[2*l],   zv1.x, a10);
                    a11 = fmaf(c1[2*l],   zv1.x, a11);
                    a00 = fmaf(c0[2*l+1], zv0.y, a00);
                    a01 = fmaf(c1[2*l+1], zv0.y, a01);
                    a10 = fmaf(c0[2*l+1], zv1.y, a10);
                    a11 = fmaf(c1[2*l+1], zv1.y, a11);
                }
                {
                    int cell = cells[cc + i];
                    float s = sfs[cc + i];
                    float2 o; o.x = softplus_f(a00) * s; o.y = softplus_f(a01) * s;
                    *(float2*)(out + (size_t)cell * G + g0) = o;   // STG.64 coalesced
                }
                if (two) {
                    int cell = cells[cc + i + 1];
                    float s = sfs[cc + i + 1];
                    float2 o; o.x = softplus_f(a10) * s; o.y = softplus_f(a11) * s;
                    *(float2*)(out + (size_t)cell * G + g0) = o;
                }
            }
        }
    }
}

// ---------------------------------------------------------------------------
// Inputs (metadata order): z, batch_covariate, size_factor, W_amat, A_emb,
//                          b_emb, px_r.  Output: mean [N,G] ++ inv_disp [G].
// ---------------------------------------------------------------------------
extern "C" void kernel_launch(void* const* d_in, const int* in_sizes, int n_in,
                              void* d_out, int out_size) {
    const float* z    = (const float*)d_in[0];
    const int*   bc   = (const int*)  d_in[1];
    const float* sf   = (const float*)d_in[2];
    const float* W    = (const float*)d_in[3];
    const float* A    = (const float*)d_in[4];
    const float* bemb = (const float*)d_in[5];
    const float* px_r = (const float*)d_in[6];
    float* out = (float*)d_out;

    const int N  = in_sizes[1];        // 1024
    const int G  = in_sizes[6];        // 10000
    const int NB = in_sizes[5] / G;    // 64

    dim3 grid((G + GPB - 1) / GPB, NB + 1);
    fused_decoder_kernel<<<grid, THREADS>>>(z, bc, sf, W, A, bemb, px_r, out, N, G, NB);
}

// round 6
// speedup vs baseline: 1.1747x; 1.0462x over previous
#include <cuda_runtime.h>
#include <cuda_bf16.h>
#include <math.h>
#include <stdint.h>

// Problem constants (reference: N=1024, L=30, G=10000, NB=64)
#define LDIM    30
#define ZROW    32           // padded z row (2 zero pads) -> LDS.128 inner loop
#define GPB     256          // genes per block tile
#define HALF    128          // genes per pipeline stage (one smem buffer)
#define THREADS 128
#define NBPB    2            // batches processed per block
#define MAXC    96           // max cells per batch (N=1024,NB=64: mean 16, 96 = >>12 sigma)

__device__ __forceinline__ float softplus_fast(float x) {
    // max(x,0) + log1p(exp(-|x|)); fast intrinsics (rel err ~1e-6 << 1e-3 budget)
    return fmaxf(x, 0.0f) + __logf(1.0f + __expf(-fabsf(x)));
}

__device__ __forceinline__ void cp_async16(unsigned int saddr, const void* gptr) {
    asm volatile("cp.async.cg.shared.global [%0], [%1], 16;\n" :: "r"(saddr), "l"(gptr));
}
__device__ __forceinline__ void cp_commit() { asm volatile("cp.async.commit_group;\n" ::: "memory"); }
template<int W> __device__ __forceinline__ void cp_wait() {
    asm volatile("cp.async.wait_group %0;\n" :: "n"(W) : "memory");
}

// ---------------------------------------------------------------------------
// grid = (ceil(G/GPB), NB/NBPB + 1), block = THREADS
//   y <  NB/NBPB : decoder, gene tile x, batches [y*2, y*2+2), 4 pipelined stages
//   y == NB/NBPB : inverse_dispersion = exp(px_r)
// ---------------------------------------------------------------------------
__global__ __launch_bounds__(THREADS) void fused_decoder_kernel(
    const float* __restrict__ z,      // [N, L]
    const int*   __restrict__ bc,     // [N]
    const float* __restrict__ sf,     // [N, 1]
    const float* __restrict__ W,      // [L, G]
    const float* __restrict__ A,      // [NB, G, L]
    const float* __restrict__ bemb,   // [NB, G]
    const float* __restrict__ px_r,   // [G]
    float* __restrict__ out,          // [N, G] ++ [G]
    int N, int G, int NB)
{
    // ---- exp(px_r) slice ----
    if (blockIdx.y == (unsigned)(NB / NBPB)) {
        float* od = out + (size_t)N * G;
        for (int g = blockIdx.x * THREADS + threadIdx.x; g < G; g += gridDim.x * THREADS)
            od[g] = __expf(px_r[g]);
        return;
    }

    __shared__ float abuf[2][HALF * LDIM];     // 2 x 15 KB double-buffered A half-tiles
    __shared__ float zbuf[MAXC * ZROW];        // 12 KB  current batch's z rows (padded)
    __shared__ int   cells[NBPB][MAXC];
    __shared__ float sfs[NBPB][MAXC];
    __shared__ int   cnt[NBPB];

    const int tid   = threadIdx.x;
    const int b0    = blockIdx.y * NBPB;
    const int gbase = blockIdx.x * GPB;
    const int nst   = min(GPB, G - gbase);     // genes in this tile

    // genes covered by half h (for G=10000: 128, 128 ... last tile: 16, 0)
    auto half_genes = [&](int h) { return max(0, min(HALF, nst - h * HALF)); };

    // ---- prologue: kick off stage 0 (batch b0, half 0) before anything else ----
    {
        const int ch = half_genes(0);
        const float4* src = (const float4*)(A + ((size_t)b0 * G + gbase) * LDIM);
        unsigned int dst = (unsigned int)__cvta_generic_to_shared(&abuf[0][0]);
        const int w4 = ch * LDIM / 4;          // ch*30 is a multiple of 4 here
        for (int i = tid; i < w4; i += THREADS) cp_async16(dst + i * 16, src + i);
    }
    cp_commit();

    // ---- compact this block's 2 batches' cell lists (bc: 4KB, L1/L2-hot) ----
    if (tid < NBPB) cnt[tid] = 0;
    __syncthreads();
    for (int n = tid; n < N; n += THREADS) {
        int j = bc[n] - b0;
        if (j >= 0 && j < NBPB) {
            int p = atomicAdd(&cnt[j], 1);
            if (p < MAXC) cells[j][p] = n;
        }
    }
    __syncthreads();
    const int nc0 = min(cnt[0], MAXC);
    const int nc1 = min(cnt[1], MAXC);
    for (int i = tid; i < NBPB * MAXC; i += THREADS) {
        int j = i / MAXC, k = i - j * MAXC;
        int ncj = (j == 0) ? nc0 : nc1;
        if (k < ncj) sfs[j][k] = sf[cells[j][k]];
    }
    // (first use of sfs is after the in-loop __syncthreads)

    const int NSTAGE = NBPB * 2;
    for (int s = 0; s < NSTAGE; s++) {
        const int j = s >> 1, h = s & 1;
        const int b = b0 + j;

        // ---- prefetch next stage's A half-tile into the other buffer ----
        if (s + 1 < NSTAGE) {
            const int jn = (s + 1) >> 1, hn = (s + 1) & 1;
            const int ch = half_genes(hn);
            const float4* src = (const float4*)(A + ((size_t)(b0 + jn) * G + gbase + hn * HALF) * LDIM);
            unsigned int dst = (unsigned int)__cvta_generic_to_shared(&abuf[(s + 1) & 1][0]);
            const int w4 = ch * LDIM / 4;
            for (int i = tid; i < w4; i += THREADS) cp_async16(dst + i * 16, src + i);
            cp_commit();
            cp_wait<1>();                      // current stage's group done; next may fly
        } else {
            cp_wait<0>();
        }

        const int ncell = (j == 0) ? nc0 : nc1;

        // ---- on batch entry, stage its z rows (padded to 32, zero-filled) ----
        if (h == 0) {
            for (int i = tid; i < ncell * (LDIM / 2); i += THREADS) {
                int ci = i / (LDIM / 2), l = i - ci * (LDIM / 2);
                float2 v = *(const float2*)(z + (size_t)cells[j][ci] * LDIM + 2 * l);
                *(float2*)(zbuf + ci * ZROW + 2 * l) = v;
            }
            for (int i = tid; i < ncell; i += THREADS) {
                zbuf[i * ZROW + 30] = 0.0f;
                zbuf[i * ZROW + 31] = 0.0f;
            }
        }
        __syncthreads();   // abuf[s&1] (cp.async) + zbuf + sfs visible to all

        const int ch = half_genes(h);
        const int g  = gbase + h * HALF + tid;
        if (tid < ch && ncell > 0) {
            // combined coefficients c[l] = W[l,g] + A[b,g,l]; pads 0 (match z pads)
            float c[ZROW];
            const float* ap = &abuf[s & 1][tid * LDIM];
            #pragma unroll
            for (int l = 0; l < LDIM; l++)
                c[l] = W[(size_t)l * G + g] + ap[l];   // W coalesced, L2-hot
            c[30] = 0.0f; c[31] = 0.0f;
            const float bias = bemb[(size_t)b * G + g];

            for (int i = 0; i < ncell; i += 2) {
                const bool two = (i + 1 < ncell);
                const float4* z0 = (const float4*)(zbuf + i * ZROW);
                const float4* z1 = (const float4*)(zbuf + (two ? i + 1 : i) * ZROW);
                float a0 = bias, a1 = bias;
                #pragma unroll
                for (int q = 0; q < ZROW / 4; q++) {
                    float4 v0 = z0[q], v1 = z1[q];     // broadcast LDS.128
                    a0 = fmaf(c[4*q+0], v0.x, a0);  a1 = fmaf(c[4*q+0], v1.x, a1);
                    a0 = fmaf(c[4*q+1], v0.y, a0);  a1 = fmaf(c[4*q+1], v1.y, a1);
                    a0 = fmaf(c[4*q+2], v0.z, a0);  a1 = fmaf(c[4*q+2], v1.z, a1);
                    a0 = fmaf(c[4*q+3], v0.w, a0);  a1 = fmaf(c[4*q+3], v1.w, a1);
                }
                out[(size_t)cells[j][i] * G + g] = softplus_fast(a0) * sfs[j][i];
                if (two)
                    out[(size_t)cells[j][i + 1] * G + g] = softplus_fast(a1) * sfs[j][i + 1];
            }
        }
        __syncthreads();   // protect abuf[s&1] / zbuf before next overwrites
    }
}

// ---------------------------------------------------------------------------
// Inputs (metadata order): z, batch_covariate, size_factor, W_amat, A_emb,
//                          b_emb, px_r.  Output: mean [N,G] ++ inv_disp [G].
// ---------------------------------------------------------------------------
extern "C" void kernel_launch(void* const* d_in, const int* in_sizes, int n_in,
                              void* d_out, int out_size) {
    const float* z    = (const float*)d_in[0];
    const int*   bc   = (const int*)  d_in[1];
    const float* sf   = (const float*)d_in[2];
    const float* W    = (const float*)d_in[3];
    const float* A    = (const float*)d_in[4];
    const float* bemb = (const float*)d_in[5];
    const float* px_r = (const float*)d_in[6];
    float* out = (float*)d_out;

    const int N  = in_sizes[1];        // 1024
    const int G  = in_sizes[6];        // 10000
    const int NB = in_sizes[5] / G;    // 64 (even)

    dim3 grid((G + GPB - 1) / GPB, NB / NBPB + 1);
    fused_decoder_kernel<<<grid, THREADS>>>(z, bc, sf, W, A, bemb, px_r, out, N, G, NB);
}

// round 7
// speedup vs baseline: 1.3666x; 1.1634x over previous
#include <cuda_runtime.h>
#include <cuda_bf16.h>
#include <math.h>
#include <stdint.h>

// Problem constants (reference: N=1024, L=30, G=10000, NB=64)
#define LDIM    30
#define ZROW    32           // padded z row (2 zero pads) -> LDS.128 inner loop
#define GPB     128          // genes per block tile (= THREADS, 1 gene/thread)
#define THREADS 128
#define CHUNK   64           // cells staged per z chunk
#define NMAX    1024

__device__ __forceinline__ float softplus_fast(float x) {
    // max(x,0) + log1p(exp(-|x|)); fast intrinsics (rel err ~1e-6 << 1e-3 budget)
    return fmaxf(x, 0.0f) + __logf(1.0f + __expf(-fabsf(x)));
}

__device__ __forceinline__ void cp_async16(unsigned int saddr, const void* gptr) {
    asm volatile("cp.async.cg.shared.global [%0], [%1], 16;\n" :: "r"(saddr), "l"(gptr));
}
__device__ __forceinline__ void cp_async4(unsigned int saddr, const void* gptr) {
    asm volatile("cp.async.ca.shared.global [%0], [%1], 4;\n" :: "r"(saddr), "l"(gptr));
}
__device__ __forceinline__ void cp_commit() { asm volatile("cp.async.commit_group;\n" ::: "memory"); }
__device__ __forceinline__ void cp_wait0()  { asm volatile("cp.async.wait_group 0;\n" ::: "memory"); }

// ---------------------------------------------------------------------------
// grid = (ceil(G/GPB), NB + 1), block = 128 threads.
//   y <  NB : decoder for batch y over a 128-gene tile (small footprint,
//             8 blocks/SM -> latency hidden by inter-block overlap)
//   y == NB : inverse_dispersion = exp(px_r)
// ---------------------------------------------------------------------------
__global__ __launch_bounds__(THREADS, 8) void fused_decoder_kernel(
    const float* __restrict__ z,      // [N, L]
    const int*   __restrict__ bc,     // [N]
    const float* __restrict__ sf,     // [N, 1]
    const float* __restrict__ W,      // [L, G]
    const float* __restrict__ A,      // [NB, G, L]
    const float* __restrict__ bemb,   // [NB, G]
    const float* __restrict__ px_r,   // [G]
    float* __restrict__ out,          // [N, G] ++ [G]
    int N, int G, int NB)
{
    // ---- exp(px_r) slice ----
    if (blockIdx.y == (unsigned)NB) {
        float* od = out + (size_t)N * G;
        for (int g = blockIdx.x * THREADS + threadIdx.x; g < G; g += gridDim.x * THREADS)
            od[g] = __expf(px_r[g]);
        return;
    }

    __shared__ float as[GPB * LDIM];        // 15 KB  A tile (cp.async staged)
    __shared__ float zs[CHUNK * ZROW];      //  8 KB  z chunk, padded rows
    __shared__ int   cells[NMAX];           //  4 KB  this batch's full cell list
    __shared__ float sfs[CHUNK];
    __shared__ int   scount;

    const int tid   = threadIdx.x;
    const int b     = blockIdx.y;
    const int gbase = blockIdx.x * GPB;
    const int nst   = min(GPB, G - gbase);

    // ---- kick off A tile load first (hide behind compaction) ----
    {
        const float*  srcf = A + ((size_t)b * G + gbase) * LDIM;
        unsigned int  dst  = (unsigned int)__cvta_generic_to_shared(&as[0]);
        const int nf = nst * LDIM;
        const int w4 = nf >> 2;                       // 16B-aligned (see layout note)
        const float4* src4 = (const float4*)srcf;
        for (int i = tid; i < w4; i += THREADS) cp_async16(dst + i * 16, src4 + i);
        for (int i = w4 * 4 + tid; i < nf; i += THREADS) cp_async4(dst + i * 4, srcf + i);
    }
    cp_commit();

    // ---- compact this batch's cell list (bc: 4 KB, L1/L2-hot) ----
    if (tid == 0) scount = 0;
    __syncthreads();
    for (int n = tid; n < N; n += THREADS) {
        if (bc[n] == b) {
            int p = atomicAdd(&scount, 1);
            cells[p] = n;
        }
    }
    cp_wait0();
    __syncthreads();                       // cells/scount + as[] visible everywhere
    const int ncell = scount;
    if (ncell == 0) return;                // uniform across block

    // ---- per-thread combined coefficients c[l] = W[l,g] + A[b,g,l] ----
    const int  g   = gbase + tid;
    const bool act = (tid < nst);
    float c[ZROW];
    float bias = 0.0f;
    if (act) {
        #pragma unroll
        for (int l = 0; l < LDIM; l++)
            c[l] = W[(size_t)l * G + g] + as[tid * LDIM + l];   // W coalesced, L2-hot
        c[30] = 0.0f; c[31] = 0.0f;
        bias = bemb[(size_t)b * G + g];
    }

    for (int cc = 0; cc < ncell; cc += CHUNK) {
        const int nc = min(CHUNK, ncell - cc);
        __syncthreads();                   // previous chunk's zs reads complete
        // stage z rows (padded to 32, zero pads) + size factors
        for (int i = tid; i < nc * (LDIM / 2); i += THREADS) {
            int ci = i / (LDIM / 2), l = i - ci * (LDIM / 2);
            float2 v = *(const float2*)(z + (size_t)cells[cc + ci] * LDIM + 2 * l);
            *(float2*)(zs + ci * ZROW + 2 * l) = v;
        }
        for (int i = tid; i < nc; i += THREADS) {
            zs[i * ZROW + 30] = 0.0f;
            zs[i * ZROW + 31] = 0.0f;
            sfs[i] = sf[cells[cc + i]];
        }
        __syncthreads();

        if (act) {
            for (int i = 0; i < nc; i += 2) {
                const bool two = (i + 1 < nc);
                const float4* z0 = (const float4*)(zs + i * ZROW);
                const float4* z1 = (const float4*)(zs + (two ? i + 1 : i) * ZROW);
                float a0 = bias, a1 = bias;
                #pragma unroll
                for (int q = 0; q < ZROW / 4; q++) {
                    float4 v0 = z0[q], v1 = z1[q];         // broadcast LDS.128
                    a0 = fmaf(c[4*q+0], v0.x, a0);  a1 = fmaf(c[4*q+0], v1.x, a1);
                    a0 = fmaf(c[4*q+1], v0.y, a0);  a1 = fmaf(c[4*q+1], v1.y, a1);
                    a0 = fmaf(c[4*q+2], v0.z, a0);  a1 = fmaf(c[4*q+2], v1.z, a1);
                    a0 = fmaf(c[4*q+3], v0.w, a0);  a1 = fmaf(c[4*q+3], v1.w, a1);
                }
                float* o0 = out + (size_t)cells[cc + i] * G + g;
                *o0 = softplus_fast(a0) * sfs[i];
                if (two) {
                    float* o1 = out + (size_t)cells[cc + i + 1] * G + g;
                    *o1 = softplus_fast(a1) * sfs[i + 1];
                }
            }
        }
    }
}

// ---------------------------------------------------------------------------
// Inputs (metadata order): z, batch_covariate, size_factor, W_amat, A_emb,
//                          b_emb, px_r.  Output: mean [N,G] ++ inv_disp [G].
// ---------------------------------------------------------------------------
extern "C" void kernel_launch(void* const* d_in, const int* in_sizes, int n_in,
                              void* d_out, int out_size) {
    const float* z    = (const float*)d_in[0];
    const int*   bc   = (const int*)  d_in[1];
    const float* sf   = (const float*)d_in[2];
    const float* W    = (const float*)d_in[3];
    const float* A    = (const float*)d_in[4];
    const float* bemb = (const float*)d_in[5];
    const float* px_r = (const float*)d_in[6];
    float* out = (float*)d_out;

    const int N  = in_sizes[1];        // 1024
    const int G  = in_sizes[6];        // 10000
    const int NB = in_sizes[5] / G;    // 64

    dim3 grid((G + GPB - 1) / GPB, NB + 1);
    fused_decoder_kernel<<<grid, THREADS>>>(z, bc, sf, W, A, bemb, px_r, out, N, G, NB);
}